// round 7
// baseline (speedup 1.0000x reference)
#include <cuda_runtime.h>
#include <cuda_fp16.h>
#include <math.h>
#include <stdint.h>

#define BB   8
#define NPOS 4096
#define CC   512
#define NH   8
#define DH   64
#define KDIM 512
#define MTOT (BB * NPOS)   /* 32768 */
#define NTOT (2 * CC)      /* 1024  */

// ---------------- scratch (device globals; no allocs) ----------------
__device__ unsigned short g_qr[(size_t)MTOT * CC];    // q_rope fp16 [n][512]
__device__ unsigned short g_qf[(size_t)MTOT * CC];    // q_feat fp16 [n][512]
__device__ unsigned short g_krTh[(size_t)BB * CC * NPOS];  // k_rope^T hi [b*512+ch][n]
__device__ unsigned short g_krTl[(size_t)BB * CC * NPOS];  // k_rope^T lo
__device__ unsigned short g_xTh[(size_t)BB * CC * NPOS];   // x^T hi
__device__ unsigned short g_xTl[(size_t)BB * CC * NPOS];   // x^T lo
__device__ unsigned short g_xh[(size_t)MTOT * KDIM];  // x row-major hi
__device__ unsigned short g_xl[(size_t)MTOT * KDIM];
__device__ unsigned short g_wh[(size_t)NTOT * KDIM];
__device__ unsigned short g_wl[(size_t)NTOT * KDIM];
__device__ float g_kspart[256 * CC];                  // per-mtile k_feat col sums
__device__ float g_ksum[BB * CC];
__device__ float g_kv_part[8 * BB * NH * DH * DH];
__device__ float g_kv[BB * NH * DH * DH];

// ---------------- PTX helpers (sm_80-era only) ----------------
__device__ __forceinline__ uint32_t smem_u32(const void* p) {
    uint32_t a;
    asm("{ .reg .u64 t; cvta.to.shared.u64 t, %1; cvt.u32.u64 %0, t; }"
        : "=r"(a) : "l"(p));
    return a;
}
__device__ __forceinline__ void cpa16(uint32_t dst, const void* src) {
    asm volatile("cp.async.cg.shared.global [%0], [%1], 16;" ::"r"(dst), "l"(src));
}
#define CP_COMMIT() asm volatile("cp.async.commit_group;" ::: "memory")
#define CP_WAIT(n)  asm volatile("cp.async.wait_group %0;" ::"n"(n) : "memory")

__device__ __forceinline__ void ldmx4(uint32_t* r, uint32_t addr) {
    asm volatile("ldmatrix.sync.aligned.m8n8.x4.shared.b16 {%0,%1,%2,%3}, [%4];"
                 : "=r"(r[0]), "=r"(r[1]), "=r"(r[2]), "=r"(r[3]) : "r"(addr));
}
__device__ __forceinline__ void mma16816(float* d, const uint32_t* a,
                                         const uint32_t* b) {
    asm volatile(
        "mma.sync.aligned.m16n8k16.row.col.f32.f16.f16.f32 "
        "{%0,%1,%2,%3}, {%4,%5,%6,%7}, {%8,%9}, {%0,%1,%2,%3};"
        : "+f"(d[0]), "+f"(d[1]), "+f"(d[2]), "+f"(d[3])
        : "r"(a[0]), "r"(a[1]), "r"(a[2]), "r"(a[3]), "r"(b[0]), "r"(b[1]));
}
__device__ __forceinline__ unsigned short f2h(float v) {
    return __half_as_ushort(__float2half_rn(v));
}
__device__ __forceinline__ float h2f(unsigned short u) {
    return __half2float(__ushort_as_half(u));
}

// ============================================================================
// K0a: x -> row-major fp16 hi/lo planes AND transposed fp16 hi/lo planes
// ============================================================================
__global__ __launch_bounds__(256) void k_prep_x(const float* __restrict__ x) {
    __shared__ unsigned short s_hi[64 * 72], s_lo[64 * 72];
    int ct = blockIdx.x, nt = blockIdx.y, b = blockIdx.z;
    int n0 = nt * 64, ch0 = ct * 64;
    int tid = threadIdx.x;
#pragma unroll
    for (int i = 0; i < 4; i++) {
        int f = tid + i * 256;
        int r = f >> 4, c4 = f & 15;
        size_t ro = (size_t)(b * NPOS + n0 + r) * KDIM + ch0 + c4 * 4;
        float4 v = *(const float4*)(x + ro);
        float vv[4] = {v.x, v.y, v.z, v.w};
        unsigned short hh[4], ll[4];
#pragma unroll
        for (int t = 0; t < 4; t++) {
            __half hb = __float2half_rn(vv[t]);
            hh[t] = __half_as_ushort(hb);
            ll[t] = f2h(vv[t] - __half2float(hb));
        }
        uint2 hp, lp;
        hp.x = (uint32_t)hh[1] << 16 | hh[0];
        hp.y = (uint32_t)hh[3] << 16 | hh[2];
        lp.x = (uint32_t)ll[1] << 16 | ll[0];
        lp.y = (uint32_t)ll[3] << 16 | ll[2];
        *(uint2*)(g_xh + ro) = hp;
        *(uint2*)(g_xl + ro) = lp;
#pragma unroll
        for (int j = 0; j < 4; j++) {
            s_hi[(c4 * 4 + j) * 72 + r] = hh[j];
            s_lo[(c4 * 4 + j) * 72 + r] = ll[j];
        }
    }
    __syncthreads();
    int ch = tid >> 2, q = tid & 3;
    size_t to = (size_t)(b * CC + ch0 + ch) * NPOS + n0 + q * 16;
    const uint4* sh = (const uint4*)(s_hi + ch * 72 + q * 16);
    const uint4* sl = (const uint4*)(s_lo + ch * 72 + q * 16);
    ((uint4*)(g_xTh + to))[0] = sh[0];
    ((uint4*)(g_xTh + to))[1] = sh[1];
    ((uint4*)(g_xTl + to))[0] = sl[0];
    ((uint4*)(g_xTl + to))[1] = sl[1];
}

// ============================================================================
// K0b: Wqk -> fp16 hi/lo planes (row-major)
// ============================================================================
__global__ __launch_bounds__(256) void k_convert_w(const float* __restrict__ W) {
    int idx = blockIdx.x * 256 + threadIdx.x;
    int row = idx >> 7, q4 = idx & 127;
    size_t ro = (size_t)row * KDIM + q4 * 4;
    float4 v = *(const float4*)(W + ro);
    float vv[4] = {v.x, v.y, v.z, v.w};
    unsigned short hh[4], ll[4];
#pragma unroll
    for (int t = 0; t < 4; t++) {
        __half hb = __float2half_rn(vv[t]);
        hh[t] = __half_as_ushort(hb);
        ll[t] = f2h(vv[t] - __half2float(hb));
    }
    uint2 hp, lp;
    hp.x = (uint32_t)hh[1] << 16 | hh[0];
    hp.y = (uint32_t)hh[3] << 16 | hh[2];
    lp.x = (uint32_t)ll[1] << 16 | ll[0];
    lp.y = (uint32_t)ll[3] << 16 | ll[2];
    *(uint2*)(g_wh + ro) = hp;
    *(uint2*)(g_wl + ro) = lp;
}

// ============================================================================
// K1: HMMA split GEMM qk = x @ Wqk^T, 3-stage cp.async pipeline.
// Epilogue: bias, elu+1, RoPE; q-CTAs write fp16 q_rope/q_feat (smem-staged);
// k-CTAs write transposed fp16 hi/lo k_rope + per-mtile k_feat column sums.
// ============================================================================
#define STG_BYTES 40960          /* 4 planes * 128 rows * 80B */
#define PLN_BYTES 10240
#define GEMM_SMEM (3 * STG_BYTES)

__global__ __launch_bounds__(256) void k_gemm_mma(const float* __restrict__ bqk) {
    extern __shared__ char dsm[];
    const uint32_t smem0 = smem_u32(dsm);

    const int tid = threadIdx.x;
    const int wid = tid >> 5, lid = tid & 31;
    const int j00 = blockIdx.x * 128;
    const int m00 = blockIdx.y * 128;
    const int warp_m = (wid >> 2) * 64;
    const int n0     = (wid & 3) * 32;

    auto load_stage = [&](int it, int s) {
        const uint32_t sb = smem0 + s * STG_BYTES;
        const int k0 = it * 32;
#pragma unroll
        for (int j = 0; j < 8; j++) {
            int id = tid + j * 256;
            int mp = id >> 9;
            int r  = (id >> 2) & 127;
            int c  = id & 3;
            const unsigned short* src;
            if (mp == 0)      src = g_xh + (size_t)(m00 + r) * KDIM + k0 + c * 8;
            else if (mp == 1) src = g_xl + (size_t)(m00 + r) * KDIM + k0 + c * 8;
            else if (mp == 2) src = g_wh + (size_t)(j00 + r) * KDIM + k0 + c * 8;
            else              src = g_wl + (size_t)(j00 + r) * KDIM + k0 + c * 8;
            cpa16(sb + mp * PLN_BYTES + r * 80 + c * 16, src);
        }
    };

    float acc[4][4][4] = {};
    const int a_r = (lid & 15);
    const int a_c = (lid >> 4);
    const int b_r = (lid & 7) + ((lid >> 4) << 3);
    const int b_c = (lid >> 3) & 1;

    load_stage(0, 0); CP_COMMIT();
    load_stage(1, 1); CP_COMMIT();

    for (int it = 0; it < 16; ++it) {
        if (it < 14) {
            load_stage(it + 2, (it + 2) % 3);
            CP_COMMIT();
            CP_WAIT(2);
        } else if (it == 14) {
            CP_WAIT(1);
        } else {
            CP_WAIT(0);
        }
        __syncthreads();

        const uint32_t sb = smem0 + (it % 3) * STG_BYTES;
        const uint32_t ah_b = sb;
        const uint32_t al_b = sb + PLN_BYTES;
        const uint32_t bh_b = sb + 2 * PLN_BYTES;
        const uint32_t bl_b = sb + 3 * PLN_BYTES;

#pragma unroll
        for (int ks = 0; ks < 2; ++ks) {
            uint32_t ah[4][4], al[4][4], bh[4][2], bl[4][2];
#pragma unroll
            for (int mf = 0; mf < 4; mf++) {
                uint32_t off = (uint32_t)(warp_m + mf * 16 + a_r) * 80 +
                               (a_c + ks * 2) * 16;
                ldmx4(ah[mf], ah_b + off);
                ldmx4(al[mf], al_b + off);
            }
#pragma unroll
            for (int nf2 = 0; nf2 < 2; nf2++) {
                uint32_t off = (uint32_t)(n0 + nf2 * 16 + b_r) * 80 +
                               (b_c + ks * 2) * 16;
                uint32_t t[4];
                ldmx4(t, bh_b + off);
                bh[nf2 * 2][0] = t[0]; bh[nf2 * 2][1] = t[1];
                bh[nf2 * 2 + 1][0] = t[2]; bh[nf2 * 2 + 1][1] = t[3];
                ldmx4(t, bl_b + off);
                bl[nf2 * 2][0] = t[0]; bl[nf2 * 2][1] = t[1];
                bl[nf2 * 2 + 1][0] = t[2]; bl[nf2 * 2 + 1][1] = t[3];
            }
#pragma unroll
            for (int mf = 0; mf < 4; mf++)
#pragma unroll
                for (int nf = 0; nf < 4; nf++) {
                    mma16816(acc[mf][nf], ah[mf], bh[nf]);
                    mma16816(acc[mf][nf], al[mf], bh[nf]);
                    mma16816(acc[mf][nf], ah[mf], bl[nf]);
                }
        }
        __syncthreads();
    }

    // ---------------- epilogue ----------------
    unsigned short* s_p0 = (unsigned short*)dsm;               // 128x136
    unsigned short* s_p1 = s_p0 + 128 * 136;
    float*          s_red = (float*)(s_p1 + 128 * 136);        // 2x128

    const bool is_k = (j00 >= CC);
    const int  jbase = (is_k ? j00 - CC : j00) + n0 + 2 * (lid & 3);
    float th[4], bx[4], by[4];
    bool  uhc[4];
#pragma unroll
    for (int nf = 0; nf < 4; nf++) {
        int jch = jbase + nf * 8;
        int j2  = jch >> 1;
        int jm  = j2 & 127;
        th[nf]  = exp2f(-(float)jm * (13.287712379549449f / 128.0f));
        uhc[nf] = (j2 < 128);
        float2 bv = *(const float2*)(bqk + j00 + n0 + nf * 8 + 2 * (lid & 3));
        bx[nf] = bv.x;
        by[nf] = bv.y;
    }

    float fsum[4][2] = {};
#pragma unroll
    for (int mf = 0; mf < 4; mf++)
#pragma unroll
        for (int ri = 0; ri < 2; ri++) {
            int   r_loc = warp_m + mf * 16 + (lid >> 2) + ri * 8;
            int   n  = (m00 + r_loc) & (NPOS - 1);
            float hf = (float)(n >> 6);
            float wf = (float)(n & 63);
#pragma unroll
            for (int nf = 0; nf < 4; nf++) {
                float v0 = acc[mf][nf][ri * 2 + 0] + bx[nf];
                float v1 = acc[mf][nf][ri * 2 + 1] + by[nf];
                float f0 = (v0 > 0.f) ? (v0 + 1.f) : __expf(v0);
                float f1 = (v1 > 0.f) ? (v1 + 1.f) : __expf(v1);
                float s, c;
                __sincosf((uhc[nf] ? hf : wf) * th[nf], &s, &c);
                float ro0 = c * f0 - s * f1;
                float ro1 = c * f1 + s * f0;
                int c_loc = n0 + nf * 8 + 2 * (lid & 3);
                if (!is_k) {
                    s_p0[r_loc * 136 + c_loc]     = f2h(ro0);
                    s_p0[r_loc * 136 + c_loc + 1] = f2h(ro1);
                    s_p1[r_loc * 136 + c_loc]     = f2h(f0);
                    s_p1[r_loc * 136 + c_loc + 1] = f2h(f1);
                } else {
                    __half h0 = __float2half_rn(ro0);
                    __half h1 = __float2half_rn(ro1);
                    s_p0[c_loc * 136 + r_loc]       = __half_as_ushort(h0);
                    s_p1[c_loc * 136 + r_loc]       = f2h(ro0 - __half2float(h0));
                    s_p0[(c_loc + 1) * 136 + r_loc] = __half_as_ushort(h1);
                    s_p1[(c_loc + 1) * 136 + r_loc] = f2h(ro1 - __half2float(h1));
                    fsum[nf][0] += f0;
                    fsum[nf][1] += f1;
                }
            }
        }

    if (is_k) {
#pragma unroll
        for (int off = 4; off < 32; off <<= 1)
#pragma unroll
            for (int nf = 0; nf < 4; nf++) {
                fsum[nf][0] += __shfl_xor_sync(0xffffffffu, fsum[nf][0], off);
                fsum[nf][1] += __shfl_xor_sync(0xffffffffu, fsum[nf][1], off);
            }
        if (lid < 4) {
#pragma unroll
            for (int nf = 0; nf < 4; nf++) {
                s_red[(wid >> 2) * 128 + n0 + nf * 8 + 2 * lid]     = fsum[nf][0];
                s_red[(wid >> 2) * 128 + n0 + nf * 8 + 2 * lid + 1] = fsum[nf][1];
            }
        }
    }
    __syncthreads();

    const int r    = tid >> 1;
    const int half = tid & 1;
    if (!is_k) {
        size_t drow = (size_t)(m00 + r) * CC + j00 + half * 64;
        const uint4* sp0 = (const uint4*)(s_p0 + r * 136 + half * 64);
        const uint4* sp1 = (const uint4*)(s_p1 + r * 136 + half * 64);
        uint4* d0 = (uint4*)(g_qr + drow);
        uint4* d1 = (uint4*)(g_qf + drow);
#pragma unroll
        for (int i = 0; i < 8; i++) { d0[i] = sp0[i]; d1[i] = sp1[i]; }
    } else {
        const int b      = m00 >> 12;
        const int n0g    = m00 & (NPOS - 1);
        const int chbase = (blockIdx.x - 4) * 128;
        size_t drow = (size_t)(b * CC + chbase + r) * NPOS + n0g + half * 64;
        const uint4* sp0 = (const uint4*)(s_p0 + r * 136 + half * 64);
        const uint4* sp1 = (const uint4*)(s_p1 + r * 136 + half * 64);
        uint4* d0 = (uint4*)(g_krTh + drow);
        uint4* d1 = (uint4*)(g_krTl + drow);
#pragma unroll
        for (int i = 0; i < 8; i++) { d0[i] = sp0[i]; d1[i] = sp1[i]; }
        if (tid < 128)
            g_kspart[(size_t)blockIdx.y * CC + chbase + tid] =
                s_red[tid] + s_red[128 + tid];
    }
}

// ============================================================================
// K1c: ksum final — sum 32 mtile partials per batch
// ============================================================================
__global__ void k_ksum_final() {
    int idx = blockIdx.x * 256 + threadIdx.x;  // 0..4095
    if (idx < BB * CC) {
        int b = idx >> 9, ch = idx & 511;
        float s = 0.f;
        for (int mt = b * 32; mt < b * 32 + 32; mt++)
            s += g_kspart[(size_t)mt * CC + ch];
        g_ksum[idx] = s;
    }
}

// ============================================================================
// K2: kv partials via HMMA: per (chunk,b,h): kv[64][64] += kr^T x over 512 n
// A = krT [d][n] row-major; B = xT [e][n] (col-major B). 3-term hi/lo split.
// ============================================================================
#define KV_PLN 9216              /* 64 rows * 144B */
#define KV_STG (4 * KV_PLN)      /* 36864 */
#define KV_SMEM (2 * KV_STG)     /* 73728 */

__global__ __launch_bounds__(128) void k_kv_mma() {
    extern __shared__ char ksm[];
    const uint32_t s0 = smem_u32(ksm);
    const int tid = threadIdx.x;
    const int wid = tid >> 5, lid = tid & 31;
    const int chunk = blockIdx.x;          // 0..7
    const int bh    = blockIdx.y;          // 0..63
    const int b = bh >> 3, h = bh & 7;
    const size_t rowbase = (size_t)(b * CC + h * 64);
    const int nbase = chunk * 512;

    auto load_stage = [&](int it, int s) {
        const uint32_t sb = s0 + s * KV_STG;
        const int n0 = nbase + it * 64;
#pragma unroll
        for (int j = 0; j < 16; j++) {
            int id = tid + j * 128;
            int pl = id >> 9;
            int r  = (id >> 3) & 63;
            int c  = id & 7;
            const unsigned short* base =
                (pl == 0) ? g_krTh : (pl == 1) ? g_krTl : (pl == 2) ? g_xTh : g_xTl;
            cpa16(sb + pl * KV_PLN + r * 144 + c * 16,
                  base + (rowbase + r) * NPOS + n0 + c * 8);
        }
    };

    float acc[8][4] = {};
    const int a_r = (lid & 15);
    const int a_c = (lid >> 4);
    const int b_r = (lid & 7) + ((lid >> 4) << 3);
    const int b_c = (lid >> 3) & 1;

    load_stage(0, 0); CP_COMMIT();

    for (int it = 0; it < 8; ++it) {
        if (it < 7) {
            load_stage(it + 1, (it + 1) & 1);
            CP_COMMIT();
            CP_WAIT(1);
        } else {
            CP_WAIT(0);
        }
        __syncthreads();
        const uint32_t sb = s0 + (it & 1) * KV_STG;
#pragma unroll
        for (int ks = 0; ks < 4; ++ks) {
            uint32_t ah[4], al[4];
            uint32_t aoff = (uint32_t)(wid * 16 + a_r) * 144 + ks * 32 + a_c * 16;
            ldmx4(ah, sb + aoff);
            ldmx4(al, sb + KV_PLN + aoff);
            uint32_t bhf[8][2], blf[8][2];
#pragma unroll
            for (int e2 = 0; e2 < 4; e2++) {
                uint32_t boff = (uint32_t)(e2 * 16 + b_r) * 144 + ks * 32 + b_c * 16;
                uint32_t t[4];
                ldmx4(t, sb + 2 * KV_PLN + boff);
                bhf[e2 * 2][0] = t[0]; bhf[e2 * 2][1] = t[1];
                bhf[e2 * 2 + 1][0] = t[2]; bhf[e2 * 2 + 1][1] = t[3];
                ldmx4(t, sb + 3 * KV_PLN + boff);
                blf[e2 * 2][0] = t[0]; blf[e2 * 2][1] = t[1];
                blf[e2 * 2 + 1][0] = t[2]; blf[e2 * 2 + 1][1] = t[3];
            }
#pragma unroll
            for (int ef = 0; ef < 8; ef++) {
                mma16816(acc[ef], ah, bhf[ef]);
                mma16816(acc[ef], al, bhf[ef]);
                mma16816(acc[ef], ah, blf[ef]);
            }
        }
        __syncthreads();
    }

    float* dst = g_kv_part + (size_t)(chunk * 64 + bh) * (DH * DH);
    const int r0 = wid * 16 + (lid >> 2);
    const int c0 = 2 * (lid & 3);
#pragma unroll
    for (int ef = 0; ef < 8; ef++) {
        *(float2*)&dst[r0 * DH + ef * 8 + c0] = make_float2(acc[ef][0], acc[ef][1]);
        *(float2*)&dst[(r0 + 8) * DH + ef * 8 + c0] = make_float2(acc[ef][2], acc[ef][3]);
    }
}

__global__ void k_kv_final() {
    int idx = blockIdx.x * 256 + threadIdx.x;
    float s = 0.f;
    for (int c2 = 0; c2 < 8; c2++) s += g_kv_part[(size_t)c2 * 64 * DH * DH + idx];
    g_kv[idx] = s * (1.0f / (float)NPOS);
}

// ============================================================================
// K3: out = (q_rope @ kv) * z + LePE(x)   (q_rope/q_feat now fp16)
// ============================================================================
__global__ __launch_bounds__(256) void k_out(const float* __restrict__ x,
                                             const float* __restrict__ lepe_w,
                                             const float* __restrict__ lepe_b,
                                             float* __restrict__ out) {
    __shared__ float s_kv[64 * 68];
    __shared__ float s_qrT[64 * 68];
    __shared__ float s_z[64];
    __shared__ float s_km[64];

    int ntile = blockIdx.x;
    int hh    = blockIdx.y;
    int b     = blockIdx.z;
    int tid   = threadIdx.x;
    int n0    = ntile * 64;

#pragma unroll
    for (int i = 0; i < 4; i++) {
        int f = tid + i * 256;
        int r = f >> 4, cu = f & 15;
        uint2 v = *(const uint2*)(g_qf + (size_t)(b * NPOS + n0 + r) * CC +
                                  hh * DH + cu * 4);
        s_kv[r * 68 + cu * 4 + 0] = h2f((unsigned short)(v.x & 0xffff));
        s_kv[r * 68 + cu * 4 + 1] = h2f((unsigned short)(v.x >> 16));
        s_kv[r * 68 + cu * 4 + 2] = h2f((unsigned short)(v.y & 0xffff));
        s_kv[r * 68 + cu * 4 + 3] = h2f((unsigned short)(v.y >> 16));
    }
    if (tid < 64) s_km[tid] = g_ksum[b * CC + hh * DH + tid] * (1.0f / (float)NPOS);
    __syncthreads();

    if (tid < 64) {
        float dot = 0.f;
#pragma unroll
        for (int dd = 0; dd < 64; dd++) dot += s_kv[tid * 68 + dd] * s_km[dd];
        s_z[tid] = 1.0f / (dot + 1e-6f);
    }
    __syncthreads();

#pragma unroll
    for (int i = 0; i < 4; i++) {
        int f = tid + i * 256;
        int r = f >> 4, cu = f & 15;
        *(float4*)&s_kv[r * 68 + cu * 4] =
            *(const float4*)(g_kv + (size_t)(b * NH + hh) * DH * DH + r * DH + cu * 4);
        uint2 v = *(const uint2*)(g_qr + (size_t)(b * NPOS + n0 + r) * CC +
                                  hh * DH + cu * 4);
        s_qrT[(cu * 4 + 0) * 68 + r] = h2f((unsigned short)(v.x & 0xffff));
        s_qrT[(cu * 4 + 1) * 68 + r] = h2f((unsigned short)(v.x >> 16));
        s_qrT[(cu * 4 + 2) * 68 + r] = h2f((unsigned short)(v.y & 0xffff));
        s_qrT[(cu * 4 + 3) * 68 + r] = h2f((unsigned short)(v.y >> 16));
    }
    __syncthreads();

    int ty = tid >> 4, tx = tid & 15;
    int r0 = ty * 4, e0 = tx * 4;
    float acc[4][4] = {};
#pragma unroll
    for (int dd = 0; dd < 64; dd++) {
        float4 a  = *(const float4*)&s_qrT[dd * 68 + r0];
        float4 bv = *(const float4*)&s_kv[dd * 68 + e0];
        float av[4]  = {a.x, a.y, a.z, a.w};
        float bb2[4] = {bv.x, bv.y, bv.z, bv.w};
#pragma unroll
        for (int i = 0; i < 4; i++)
#pragma unroll
            for (int j = 0; j < 4; j++) acc[i][j] += av[i] * bb2[j];
    }

    const int hi = ntile;
    float wloc[4][9], bloc[4];
#pragma unroll
    for (int j = 0; j < 4; j++) {
        int ch = hh * DH + e0 + j;
        bloc[j] = lepe_b[ch];
#pragma unroll
        for (int q = 0; q < 9; q++) wloc[j][q] = lepe_w[ch * 9 + q];
    }
#pragma unroll
    for (int ri = 0; ri < 4; ri++) {
        int r  = r0 + ri;
        int wi = r;
        int nn = n0 + r;
        float z = s_z[r];
#pragma unroll
        for (int j = 0; j < 4; j++) {
            int ch = hh * DH + e0 + j;
            float pe = bloc[j];
#pragma unroll
            for (int dy = -1; dy <= 1; dy++) {
                int y = hi + dy;
                if ((unsigned)y < 64u) {
#pragma unroll
                    for (int dx = -1; dx <= 1; dx++) {
                        int xw = wi + dx;
                        if ((unsigned)xw < 64u)
                            pe += wloc[j][(dy + 1) * 3 + dx + 1] *
                                  x[((size_t)b * NPOS + y * 64 + xw) * CC + ch];
                    }
                }
            }
            out[((size_t)b * NPOS + nn) * CC + ch] = acc[ri][j] * z + pe;
        }
    }
}

// ============================================================================
extern "C" void kernel_launch(void* const* d_in, const int* in_sizes, int n_in,
                              void* d_out, int out_size) {
    const float *x = nullptr, *Wqk = nullptr, *bqk = nullptr;
    const float *lw = nullptr, *lb = nullptr;
    for (int i = 0; i < n_in; i++) {
        switch (in_sizes[i]) {
            case BB * NPOS * CC: x   = (const float*)d_in[i]; break;
            case 2 * CC * CC:    Wqk = (const float*)d_in[i]; break;
            case 2 * CC:         bqk = (const float*)d_in[i]; break;
            case CC * 9:         lw  = (const float*)d_in[i]; break;
            case CC:             lb  = (const float*)d_in[i]; break;
            default: break;  // h, w scalars
        }
    }
    float* out = (float*)d_out;

    cudaFuncSetAttribute(k_gemm_mma, cudaFuncAttributeMaxDynamicSharedMemorySize,
                         GEMM_SMEM);
    cudaFuncSetAttribute(k_kv_mma, cudaFuncAttributeMaxDynamicSharedMemorySize,
                         KV_SMEM);

    k_prep_x<<<dim3(8, 64, 8), 256>>>(x);
    k_convert_w<<<512, 256>>>(Wqk);
    k_gemm_mma<<<dim3(8, 256), 256, GEMM_SMEM>>>(bqk);
    k_ksum_final<<<16, 256>>>();
    k_kv_mma<<<dim3(8, 64), 128, KV_SMEM>>>();
    k_kv_final<<<1024, 256>>>();
    k_out<<<dim3(64, 8, 8), 256>>>(x, lw, lb, out);
}

// round 9
// speedup vs baseline: 1.2016x; 1.2016x over previous
#include <cuda_runtime.h>
#include <cuda_fp16.h>
#include <math.h>
#include <stdint.h>

#define BB   8
#define NPOS 4096
#define CC   512
#define NH   8
#define DH   64
#define KDIM 512
#define MTOT (BB * NPOS)   /* 32768 */
#define NTOT (2 * CC)      /* 1024  */

// ---------------- scratch (device globals; no allocs) ----------------
__device__ unsigned short g_qr[(size_t)MTOT * CC];         // q_rope fp16 [n][512]
__device__ unsigned short g_qf[(size_t)MTOT * CC];         // q_feat fp16 [n][512]
__device__ unsigned short g_krT[(size_t)BB * CC * NPOS];   // k_rope^T fp16 [b*512+ch][n]
__device__ unsigned short g_xT[(size_t)BB * CC * NPOS];    // x^T fp16
__device__ unsigned short g_xh[(size_t)MTOT * KDIM];       // x row-major fp16
__device__ unsigned short g_wh[(size_t)NTOT * KDIM];       // Wqk fp16
__device__ float g_kspart[256 * CC];                       // per-mtile k_feat col sums
__device__ float g_ksum[BB * CC];
__device__ float g_kv_part[8 * BB * NH * DH * DH];
__device__ float g_kv[BB * NH * DH * DH];

// ---------------- PTX helpers (sm_80-era only) ----------------
__device__ __forceinline__ uint32_t smem_u32(const void* p) {
    uint32_t a;
    asm("{ .reg .u64 t; cvta.to.shared.u64 t, %1; cvt.u32.u64 %0, t; }"
        : "=r"(a) : "l"(p));
    return a;
}
__device__ __forceinline__ void cpa16(uint32_t dst, const void* src) {
    asm volatile("cp.async.cg.shared.global [%0], [%1], 16;" ::"r"(dst), "l"(src));
}
#define CP_COMMIT() asm volatile("cp.async.commit_group;" ::: "memory")
#define CP_WAIT(n)  asm volatile("cp.async.wait_group %0;" ::"n"(n) : "memory")

__device__ __forceinline__ void ldmx4(uint32_t* r, uint32_t addr) {
    asm volatile("ldmatrix.sync.aligned.m8n8.x4.shared.b16 {%0,%1,%2,%3}, [%4];"
                 : "=r"(r[0]), "=r"(r[1]), "=r"(r[2]), "=r"(r[3]) : "r"(addr));
}
__device__ __forceinline__ void mma16816(float* d, const uint32_t* a,
                                         const uint32_t* b) {
    asm volatile(
        "mma.sync.aligned.m16n8k16.row.col.f32.f16.f16.f32 "
        "{%0,%1,%2,%3}, {%4,%5,%6,%7}, {%8,%9}, {%0,%1,%2,%3};"
        : "+f"(d[0]), "+f"(d[1]), "+f"(d[2]), "+f"(d[3])
        : "r"(a[0]), "r"(a[1]), "r"(a[2]), "r"(a[3]), "r"(b[0]), "r"(b[1]));
}
__device__ __forceinline__ unsigned short f2h(float v) {
    return __half_as_ushort(__float2half_rn(v));
}
__device__ __forceinline__ float h2f(unsigned short u) {
    return __half2float(__ushort_as_half(u));
}

// ============================================================================
// K0a: x -> row-major fp16 plane AND transposed fp16 plane
// ============================================================================
__global__ __launch_bounds__(256) void k_prep_x(const float* __restrict__ x) {
    __shared__ unsigned short s_hi[64 * 72];
    int ct = blockIdx.x, nt = blockIdx.y, b = blockIdx.z;
    int n0 = nt * 64, ch0 = ct * 64;
    int tid = threadIdx.x;
#pragma unroll
    for (int i = 0; i < 4; i++) {
        int f = tid + i * 256;
        int r = f >> 4, c4 = f & 15;
        size_t ro = (size_t)(b * NPOS + n0 + r) * KDIM + ch0 + c4 * 4;
        float4 v = *(const float4*)(x + ro);
        float vv[4] = {v.x, v.y, v.z, v.w};
        unsigned short hh[4];
#pragma unroll
        for (int t = 0; t < 4; t++) hh[t] = f2h(vv[t]);
        uint2 hp;
        hp.x = (uint32_t)hh[1] << 16 | hh[0];
        hp.y = (uint32_t)hh[3] << 16 | hh[2];
        *(uint2*)(g_xh + ro) = hp;
#pragma unroll
        for (int j = 0; j < 4; j++) s_hi[(c4 * 4 + j) * 72 + r] = hh[j];
    }
    __syncthreads();
    int ch = tid >> 2, q = tid & 3;
    size_t to = (size_t)(b * CC + ch0 + ch) * NPOS + n0 + q * 16;
    const uint4* sh = (const uint4*)(s_hi + ch * 72 + q * 16);
    ((uint4*)(g_xT + to))[0] = sh[0];
    ((uint4*)(g_xT + to))[1] = sh[1];
}

// ============================================================================
// K0b: Wqk -> fp16 plane (row-major)
// ============================================================================
__global__ __launch_bounds__(256) void k_convert_w(const float* __restrict__ W) {
    int idx = blockIdx.x * 256 + threadIdx.x;
    int row = idx >> 7, q4 = idx & 127;
    size_t ro = (size_t)row * KDIM + q4 * 4;
    float4 v = *(const float4*)(W + ro);
    unsigned short hh[4] = {f2h(v.x), f2h(v.y), f2h(v.z), f2h(v.w)};
    uint2 hp;
    hp.x = (uint32_t)hh[1] << 16 | hh[0];
    hp.y = (uint32_t)hh[3] << 16 | hh[2];
    *(uint2*)(g_wh + ro) = hp;
}

// ============================================================================
// K1: HMMA fp16 GEMM qk = x @ Wqk^T, 3-stage cp.async pipeline.
// Epilogue: bias, elu+1, RoPE; q-CTAs write fp16 q_rope/q_feat (smem-staged);
// k-CTAs write transposed fp16 k_rope + per-mtile k_feat column sums.
// ============================================================================
#define STG_BYTES 20480          /* 2 planes * 128 rows * 80B */
#define PLN_BYTES 10240
#define GEMM_SMEM 70656          /* max(3 stages, epilogue staging) */

__global__ __launch_bounds__(256, 2) void k_gemm_mma(const float* __restrict__ bqk) {
    extern __shared__ char dsm[];
    const uint32_t smem0 = smem_u32(dsm);

    const int tid = threadIdx.x;
    const int wid = tid >> 5, lid = tid & 31;
    const int j00 = blockIdx.x * 128;
    const int m00 = blockIdx.y * 128;
    const int warp_m = (wid >> 2) * 64;
    const int n0     = (wid & 3) * 32;

    auto load_stage = [&](int it, int s) {
        const uint32_t sb = smem0 + s * STG_BYTES;
        const int k0 = it * 32;
#pragma unroll
        for (int j = 0; j < 4; j++) {
            int id = tid + j * 256;
            int mp = id >> 9;           // 0=A 1=B
            int r  = (id >> 2) & 127;
            int c  = id & 3;
            const unsigned short* src =
                mp ? (g_wh + (size_t)(j00 + r) * KDIM + k0 + c * 8)
                   : (g_xh + (size_t)(m00 + r) * KDIM + k0 + c * 8);
            cpa16(sb + mp * PLN_BYTES + r * 80 + c * 16, src);
        }
    };

    float acc[4][4][4] = {};
    const int a_r = (lid & 15);
    const int a_c = (lid >> 4);
    const int b_r = (lid & 7) + ((lid >> 4) << 3);
    const int b_c = (lid >> 3) & 1;

    load_stage(0, 0); CP_COMMIT();
    load_stage(1, 1); CP_COMMIT();

    for (int it = 0; it < 16; ++it) {
        if (it < 14) {
            load_stage(it + 2, (it + 2) % 3);
            CP_COMMIT();
            CP_WAIT(2);
        } else if (it == 14) {
            CP_WAIT(1);
        } else {
            CP_WAIT(0);
        }
        __syncthreads();

        const uint32_t sb   = smem0 + (it % 3) * STG_BYTES;
        const uint32_t bh_b = sb + PLN_BYTES;

#pragma unroll
        for (int ks = 0; ks < 2; ++ks) {
            uint32_t ah[4][4], bh[4][2];
#pragma unroll
            for (int mf = 0; mf < 4; mf++) {
                uint32_t off = (uint32_t)(warp_m + mf * 16 + a_r) * 80 +
                               (a_c + ks * 2) * 16;
                ldmx4(ah[mf], sb + off);
            }
#pragma unroll
            for (int nf2 = 0; nf2 < 2; nf2++) {
                uint32_t off = (uint32_t)(n0 + nf2 * 16 + b_r) * 80 +
                               (b_c + ks * 2) * 16;
                uint32_t t[4];
                ldmx4(t, bh_b + off);
                bh[nf2 * 2][0] = t[0]; bh[nf2 * 2][1] = t[1];
                bh[nf2 * 2 + 1][0] = t[2]; bh[nf2 * 2 + 1][1] = t[3];
            }
#pragma unroll
            for (int mf = 0; mf < 4; mf++)
#pragma unroll
                for (int nf = 0; nf < 4; nf++)
                    mma16816(acc[mf][nf], ah[mf], bh[nf]);
        }
        __syncthreads();
    }

    // ---------------- epilogue ----------------
    unsigned short* s_p0 = (unsigned short*)dsm;               // 128x136
    unsigned short* s_p1 = s_p0 + 128 * 136;
    float*          s_red = (float*)(s_p1 + 128 * 136);        // 2x128

    const bool is_k = (j00 >= CC);
    const int  jbase = (is_k ? j00 - CC : j00) + n0 + 2 * (lid & 3);
    float th[4], bx[4], by[4];
    bool  uhc[4];
#pragma unroll
    for (int nf = 0; nf < 4; nf++) {
        int jch = jbase + nf * 8;
        int j2  = jch >> 1;
        int jm  = j2 & 127;
        th[nf]  = exp2f(-(float)jm * (13.287712379549449f / 128.0f));
        uhc[nf] = (j2 < 128);
        float2 bv = *(const float2*)(bqk + j00 + n0 + nf * 8 + 2 * (lid & 3));
        bx[nf] = bv.x;
        by[nf] = bv.y;
    }

    float fsum[4][2] = {};
#pragma unroll
    for (int mf = 0; mf < 4; mf++)
#pragma unroll
        for (int ri = 0; ri < 2; ri++) {
            int   r_loc = warp_m + mf * 16 + (lid >> 2) + ri * 8;
            int   n  = (m00 + r_loc) & (NPOS - 1);
            float hf = (float)(n >> 6);
            float wf = (float)(n & 63);
#pragma unroll
            for (int nf = 0; nf < 4; nf++) {
                float v0 = acc[mf][nf][ri * 2 + 0] + bx[nf];
                float v1 = acc[mf][nf][ri * 2 + 1] + by[nf];
                float f0 = (v0 > 0.f) ? (v0 + 1.f) : __expf(v0);
                float f1 = (v1 > 0.f) ? (v1 + 1.f) : __expf(v1);
                float s, c;
                __sincosf((uhc[nf] ? hf : wf) * th[nf], &s, &c);
                float ro0 = c * f0 - s * f1;
                float ro1 = c * f1 + s * f0;
                int c_loc = n0 + nf * 8 + 2 * (lid & 3);
                if (!is_k) {
                    s_p0[r_loc * 136 + c_loc]     = f2h(ro0);
                    s_p0[r_loc * 136 + c_loc + 1] = f2h(ro1);
                    s_p1[r_loc * 136 + c_loc]     = f2h(f0);
                    s_p1[r_loc * 136 + c_loc + 1] = f2h(f1);
                } else {
                    s_p0[c_loc * 136 + r_loc]       = f2h(ro0);
                    s_p0[(c_loc + 1) * 136 + r_loc] = f2h(ro1);
                    fsum[nf][0] += f0;
                    fsum[nf][1] += f1;
                }
            }
        }

    if (is_k) {
#pragma unroll
        for (int off = 4; off < 32; off <<= 1)
#pragma unroll
            for (int nf = 0; nf < 4; nf++) {
                fsum[nf][0] += __shfl_xor_sync(0xffffffffu, fsum[nf][0], off);
                fsum[nf][1] += __shfl_xor_sync(0xffffffffu, fsum[nf][1], off);
            }
        if (lid < 4) {
#pragma unroll
            for (int nf = 0; nf < 4; nf++) {
                s_red[(wid >> 2) * 128 + n0 + nf * 8 + 2 * lid]     = fsum[nf][0];
                s_red[(wid >> 2) * 128 + n0 + nf * 8 + 2 * lid + 1] = fsum[nf][1];
            }
        }
    }
    __syncthreads();

    const int r    = tid >> 1;
    const int half = tid & 1;
    if (!is_k) {
        size_t drow = (size_t)(m00 + r) * CC + j00 + half * 64;
        const uint4* sp0 = (const uint4*)(s_p0 + r * 136 + half * 64);
        const uint4* sp1 = (const uint4*)(s_p1 + r * 136 + half * 64);
        uint4* d0 = (uint4*)(g_qr + drow);
        uint4* d1 = (uint4*)(g_qf + drow);
#pragma unroll
        for (int i = 0; i < 8; i++) { d0[i] = sp0[i]; d1[i] = sp1[i]; }
    } else {
        const int b      = m00 >> 12;
        const int n0g    = m00 & (NPOS - 1);
        const int chbase = (blockIdx.x - 4) * 128;
        size_t drow = (size_t)(b * CC + chbase + r) * NPOS + n0g + half * 64;
        const uint4* sp0 = (const uint4*)(s_p0 + r * 136 + half * 64);
        uint4* d0 = (uint4*)(g_krT + drow);
#pragma unroll
        for (int i = 0; i < 8; i++) d0[i] = sp0[i];
        if (tid < 128)
            g_kspart[(size_t)blockIdx.y * CC + chbase + tid] =
                s_red[tid] + s_red[128 + tid];
    }
}

// ============================================================================
// K1c: ksum final — sum 32 mtile partials per batch
// ============================================================================
__global__ void k_ksum_final() {
    int idx = blockIdx.x * 256 + threadIdx.x;  // 0..4095
    if (idx < BB * CC) {
        int b = idx >> 9, ch = idx & 511;
        float s = 0.f;
        for (int mt = b * 32; mt < b * 32 + 32; mt++)
            s += g_kspart[(size_t)mt * CC + ch];
        g_ksum[idx] = s;
    }
}

// ============================================================================
// K2: kv partials via HMMA: per (chunk,b,h): kv[64][64] += kr^T x over 512 n
// A = krT [d][n] row-major; B = xT [e][n] (col-major B). Pure fp16.
// ============================================================================
#define KV_PLN 9216              /* 64 rows * 144B */
#define KV_STG (2 * KV_PLN)      /* 18432 */
#define KV_SMEM (2 * KV_STG)     /* 36864 */

__global__ __launch_bounds__(128) void k_kv_mma() {
    extern __shared__ char ksm[];
    const uint32_t s0 = smem_u32(ksm);
    const int tid = threadIdx.x;
    const int wid = tid >> 5, lid = tid & 31;
    const int chunk = blockIdx.x;          // 0..7
    const int bh    = blockIdx.y;          // 0..63
    const int b = bh >> 3, h = bh & 7;
    const size_t rowbase = (size_t)(b * CC + h * 64);
    const int nbase = chunk * 512;

    auto load_stage = [&](int it, int s) {
        const uint32_t sb = s0 + s * KV_STG;
        const int n0 = nbase + it * 64;
#pragma unroll
        for (int j = 0; j < 8; j++) {
            int id = tid + j * 128;
            int pl = id >> 9;              // 0=krT 1=xT
            int r  = (id >> 3) & 63;
            int c  = id & 7;
            const unsigned short* base = pl ? g_xT : g_krT;
            cpa16(sb + pl * KV_PLN + r * 144 + c * 16,
                  base + (rowbase + r) * NPOS + n0 + c * 8);
        }
    };

    float acc[8][4] = {};
    const int a_r = (lid & 15);
    const int a_c = (lid >> 4);
    const int b_r = (lid & 7) + ((lid >> 4) << 3);
    const int b_c = (lid >> 3) & 1;

    load_stage(0, 0); CP_COMMIT();

    for (int it = 0; it < 8; ++it) {
        if (it < 7) {
            load_stage(it + 1, (it + 1) & 1);
            CP_COMMIT();
            CP_WAIT(1);
        } else {
            CP_WAIT(0);
        }
        __syncthreads();
        const uint32_t sb = s0 + (it & 1) * KV_STG;
#pragma unroll
        for (int ks = 0; ks < 4; ++ks) {
            uint32_t ah[4];
            uint32_t aoff = (uint32_t)(wid * 16 + a_r) * 144 + ks * 32 + a_c * 16;
            ldmx4(ah, sb + aoff);
            uint32_t bhf[8][2];
#pragma unroll
            for (int e2 = 0; e2 < 4; e2++) {
                uint32_t boff = (uint32_t)(e2 * 16 + b_r) * 144 + ks * 32 + b_c * 16;
                uint32_t t[4];
                ldmx4(t, sb + KV_PLN + boff);
                bhf[e2 * 2][0] = t[0]; bhf[e2 * 2][1] = t[1];
                bhf[e2 * 2 + 1][0] = t[2]; bhf[e2 * 2 + 1][1] = t[3];
            }
#pragma unroll
            for (int ef = 0; ef < 8; ef++) mma16816(acc[ef], ah, bhf[ef]);
        }
        __syncthreads();
    }

    float* dst = g_kv_part + (size_t)(chunk * 64 + bh) * (DH * DH);
    const int r0 = wid * 16 + (lid >> 2);
    const int c0 = 2 * (lid & 3);
#pragma unroll
    for (int ef = 0; ef < 8; ef++) {
        *(float2*)&dst[r0 * DH + ef * 8 + c0] = make_float2(acc[ef][0], acc[ef][1]);
        *(float2*)&dst[(r0 + 8) * DH + ef * 8 + c0] = make_float2(acc[ef][2], acc[ef][3]);
    }
}

__global__ void k_kv_final() {
    int idx = blockIdx.x * 256 + threadIdx.x;
    float s = 0.f;
    for (int c2 = 0; c2 < 8; c2++) s += g_kv_part[(size_t)c2 * 64 * DH * DH + idx];
    g_kv[idx] = s * (1.0f / (float)NPOS);
}

// ============================================================================
// K3: out = (q_rope @ kv) * z + LePE(x)   (q_rope/q_feat fp16)
// ============================================================================
__global__ __launch_bounds__(256) void k_out(const float* __restrict__ x,
                                             const float* __restrict__ lepe_w,
                                             const float* __restrict__ lepe_b,
                                             float* __restrict__ out) {
    __shared__ float s_kv[64 * 68];
    __shared__ float s_qrT[64 * 68];
    __shared__ float s_z[64];
    __shared__ float s_km[64];

    int ntile = blockIdx.x;
    int hh    = blockIdx.y;
    int b     = blockIdx.z;
    int tid   = threadIdx.x;
    int n0    = ntile * 64;

#pragma unroll
    for (int i = 0; i < 4; i++) {
        int f = tid + i * 256;
        int r = f >> 4, cu = f & 15;
        uint2 v = *(const uint2*)(g_qf + (size_t)(b * NPOS + n0 + r) * CC +
                                  hh * DH + cu * 4);
        s_kv[r * 68 + cu * 4 + 0] = h2f((unsigned short)(v.x & 0xffff));
        s_kv[r * 68 + cu * 4 + 1] = h2f((unsigned short)(v.x >> 16));
        s_kv[r * 68 + cu * 4 + 2] = h2f((unsigned short)(v.y & 0xffff));
        s_kv[r * 68 + cu * 4 + 3] = h2f((unsigned short)(v.y >> 16));
    }
    if (tid < 64) s_km[tid] = g_ksum[b * CC + hh * DH + tid] * (1.0f / (float)NPOS);
    __syncthreads();

    if (tid < 64) {
        float dot = 0.f;
#pragma unroll
        for (int dd = 0; dd < 64; dd++) dot += s_kv[tid * 68 + dd] * s_km[dd];
        s_z[tid] = 1.0f / (dot + 1e-6f);
    }
    __syncthreads();

#pragma unroll
    for (int i = 0; i < 4; i++) {
        int f = tid + i * 256;
        int r = f >> 4, cu = f & 15;
        *(float4*)&s_kv[r * 68 + cu * 4] =
            *(const float4*)(g_kv + (size_t)(b * NH + hh) * DH * DH + r * DH + cu * 4);
        uint2 v = *(const uint2*)(g_qr + (size_t)(b * NPOS + n0 + r) * CC +
                                  hh * DH + cu * 4);
        s_qrT[(cu * 4 + 0) * 68 + r] = h2f((unsigned short)(v.x & 0xffff));
        s_qrT[(cu * 4 + 1) * 68 + r] = h2f((unsigned short)(v.x >> 16));
        s_qrT[(cu * 4 + 2) * 68 + r] = h2f((unsigned short)(v.y & 0xffff));
        s_qrT[(cu * 4 + 3) * 68 + r] = h2f((unsigned short)(v.y >> 16));
    }
    __syncthreads();

    int ty = tid >> 4, tx = tid & 15;
    int r0 = ty * 4, e0 = tx * 4;
    float acc[4][4] = {};
#pragma unroll
    for (int dd = 0; dd < 64; dd++) {
        float4 a  = *(const float4*)&s_qrT[dd * 68 + r0];
        float4 bv = *(const float4*)&s_kv[dd * 68 + e0];
        float av[4]  = {a.x, a.y, a.z, a.w};
        float bb2[4] = {bv.x, bv.y, bv.z, bv.w};
#pragma unroll
        for (int i = 0; i < 4; i++)
#pragma unroll
            for (int j = 0; j < 4; j++) acc[i][j] += av[i] * bb2[j];
    }

    const int hi = ntile;
    float wloc[4][9], bloc[4];
#pragma unroll
    for (int j = 0; j < 4; j++) {
        int ch = hh * DH + e0 + j;
        bloc[j] = lepe_b[ch];
#pragma unroll
        for (int q = 0; q < 9; q++) wloc[j][q] = lepe_w[ch * 9 + q];
    }
#pragma unroll
    for (int ri = 0; ri < 4; ri++) {
        int r  = r0 + ri;
        int wi = r;
        int nn = n0 + r;
        float z = s_z[r];
#pragma unroll
        for (int j = 0; j < 4; j++) {
            int ch = hh * DH + e0 + j;
            float pe = bloc[j];
#pragma unroll
            for (int dy = -1; dy <= 1; dy++) {
                int y = hi + dy;
                if ((unsigned)y < 64u) {
#pragma unroll
                    for (int dx = -1; dx <= 1; dx++) {
                        int xw = wi + dx;
                        if ((unsigned)xw < 64u)
                            pe += wloc[j][(dy + 1) * 3 + dx + 1] *
                                  x[((size_t)b * NPOS + y * 64 + xw) * CC + ch];
                    }
                }
            }
            out[((size_t)b * NPOS + nn) * CC + ch] = acc[ri][j] * z + pe;
        }
    }
}

// ============================================================================
extern "C" void kernel_launch(void* const* d_in, const int* in_sizes, int n_in,
                              void* d_out, int out_size) {
    const float *x = nullptr, *Wqk = nullptr, *bqk = nullptr;
    const float *lw = nullptr, *lb = nullptr;
    for (int i = 0; i < n_in; i++) {
        switch (in_sizes[i]) {
            case BB * NPOS * CC: x   = (const float*)d_in[i]; break;
            case 2 * CC * CC:    Wqk = (const float*)d_in[i]; break;
            case 2 * CC:         bqk = (const float*)d_in[i]; break;
            case CC * 9:         lw  = (const float*)d_in[i]; break;
            case CC:             lb  = (const float*)d_in[i]; break;
            default: break;  // h, w scalars
        }
    }
    float* out = (float*)d_out;

    cudaFuncSetAttribute(k_gemm_mma, cudaFuncAttributeMaxDynamicSharedMemorySize,
                         GEMM_SMEM);
    cudaFuncSetAttribute(k_kv_mma, cudaFuncAttributeMaxDynamicSharedMemorySize,
                         KV_SMEM);

    k_prep_x<<<dim3(8, 64, 8), 256>>>(x);
    k_convert_w<<<512, 256>>>(Wqk);
    k_gemm_mma<<<dim3(8, 256), 256, GEMM_SMEM>>>(bqk);
    k_ksum_final<<<16, 256>>>();
    k_kv_mma<<<dim3(8, 64), 128, KV_SMEM>>>();
    k_kv_final<<<1024, 256>>>();
    k_out<<<dim3(64, 8, 8), 256>>>(x, lw, lb, out);
}

// round 10
// speedup vs baseline: 1.9490x; 1.6220x over previous
#include <cuda_runtime.h>
#include <cuda_fp16.h>
#include <math.h>
#include <stdint.h>

#define BB   8
#define NPOS 4096
#define CC   512
#define NH   8
#define DH   64
#define KDIM 512
#define MTOT (BB * NPOS)   /* 32768 */
#define NTOT (2 * CC)      /* 1024  */

// ---------------- scratch (device globals; no allocs) ----------------
__device__ unsigned short g_qr[(size_t)MTOT * CC];   // q_rope fp16 [n][512]
__device__ unsigned short g_qf[(size_t)MTOT * CC];   // q_feat fp16 [n][512]
// GEMM A: 256 mtiles x 8 kchunks x (128 rows x 64 halves, SW128) = 16KB blocks
__device__ unsigned short g_xA[(size_t)MTOT * KDIM];
// GEMM B: 8 jtiles x 8 kchunks x 16KB blocks
__device__ unsigned short g_wB[(size_t)NTOT * KDIM];
// kv operands: tiled (b*8+chblk)*64+nchunk -> (64 ch x 64 n, SW128) 8KB blocks
__device__ unsigned short g_krT[(size_t)BB * CC * NPOS];
__device__ unsigned short g_xT[(size_t)BB * CC * NPOS];
__device__ float g_kspart[256 * CC];
__device__ float g_ksum[BB * CC];
__device__ float g_kv_part[8 * BB * NH * DH * DH];
__device__ float g_kv[BB * NH * DH * DH];

// ---------------- PTX helpers (sm_90-baseline, no 'a'-gated features) -------
__device__ __forceinline__ uint32_t smem_u32(const void* p) {
    uint32_t a;
    asm("{ .reg .u64 t; cvta.to.shared.u64 t, %1; cvt.u32.u64 %0, t; }"
        : "=r"(a) : "l"(p));
    return a;
}
#define MBAR_INIT(a, c) \
    asm volatile("mbarrier.init.shared.b64 [%0], %1;" ::"r"(a), "r"(c) : "memory")
#define MBAR_EXPECT_TX(a, n) \
    asm volatile("mbarrier.arrive.expect_tx.shared.b64 _, [%0], %1;" ::"r"(a), "r"(n) : "memory")
#define MBAR_WAIT(addr, parity) do {                                          \
    uint32_t _m = (uint32_t)(addr);                                           \
    uint32_t _p = (uint32_t)(parity);                                         \
    asm volatile(                                                             \
        "{\n\t.reg .pred P1;\n\t"                                             \
        "WAIT_LOOP_%=:\n\t"                                                   \
        "mbarrier.try_wait.parity.acquire.cta.shared::cta.b64 P1, [%0], %1, 0x989680;\n\t" \
        "@P1 bra.uni WAIT_DONE_%=;\n\t"                                       \
        "bra.uni WAIT_LOOP_%=;\n\t"                                           \
        "WAIT_DONE_%=:\n\t}" ::"r"(_m), "r"(_p) : "memory");                  \
} while (0)
#define FENCE_ASYNC() asm volatile("fence.proxy.async.shared::cta;" ::: "memory")
__device__ __forceinline__ void bulk_g2s(uint32_t dst, const void* src,
                                         uint32_t bytes, uint32_t mbar) {
    asm volatile(
        "cp.async.bulk.shared::cluster.global.mbarrier::complete_tx::bytes "
        "[%0], [%1], %2, [%3];"
        ::"r"(dst), "l"(src), "r"(bytes), "r"(mbar) : "memory");
}
__device__ __forceinline__ void ldmx4(uint32_t* r, uint32_t addr) {
    asm volatile("ldmatrix.sync.aligned.m8n8.x4.shared.b16 {%0,%1,%2,%3}, [%4];"
                 : "=r"(r[0]), "=r"(r[1]), "=r"(r[2]), "=r"(r[3]) : "r"(addr));
}
__device__ __forceinline__ void mma16816(float* d, const uint32_t* a,
                                         const uint32_t* b) {
    asm volatile(
        "mma.sync.aligned.m16n8k16.row.col.f32.f16.f16.f32 "
        "{%0,%1,%2,%3}, {%4,%5,%6,%7}, {%8,%9}, {%0,%1,%2,%3};"
        : "+f"(d[0]), "+f"(d[1]), "+f"(d[2]), "+f"(d[3])
        : "r"(a[0]), "r"(a[1]), "r"(a[2]), "r"(a[3]), "r"(b[0]), "r"(b[1]));
}
__device__ __forceinline__ unsigned short f2h(float v) {
    return __half_as_ushort(__float2half_rn(v));
}
__device__ __forceinline__ float h2f(unsigned short u) {
    return __half2float(__ushort_as_half(u));
}
__device__ __forceinline__ uint32_t sw128(uint32_t off) {
    return off ^ ((off >> 3) & 0x70);
}

// ============================================================================
// K0a: x -> GEMM-A tiled/swizzled fp16 + kv-B (x^T) tiled/swizzled fp16
// grid (8, 64, 2) per launch; 4 launches cover b = bz0 + blockIdx.z
// ============================================================================
__global__ __launch_bounds__(256) void k_prep_x(const float* __restrict__ x,
                                                int bz0) {
    __shared__ unsigned short s_hi[64 * 72];
    int ct = blockIdx.x, nt = blockIdx.y, b = bz0 + blockIdx.z;
    int n0 = nt * 64, ch0 = ct * 64;
    int tid = threadIdx.x;
    // GEMM A tile block: mt = b*32 + nt/2, kchunk = ct, row = (nt&1)*64 + r
    const size_t abase = ((size_t)(b * 32 + (nt >> 1)) * 8 + ct) * 16384;
#pragma unroll
    for (int i = 0; i < 4; i++) {
        int f = tid + i * 256;
        int r = f >> 4, c4 = f & 15;
        size_t ro = (size_t)(b * NPOS + n0 + r) * KDIM + ch0 + c4 * 4;
        float4 v = *(const float4*)(x + ro);
        unsigned short hh[4] = {f2h(v.x), f2h(v.y), f2h(v.z), f2h(v.w)};
        uint2 hp;
        hp.x = (uint32_t)hh[1] << 16 | hh[0];
        hp.y = (uint32_t)hh[3] << 16 | hh[2];
        uint32_t row = (nt & 1) * 64 + r;
        *(uint2*)((char*)g_xA + abase + sw128(row * 128 + c4 * 8)) = hp;
#pragma unroll
        for (int j = 0; j < 4; j++) s_hi[(c4 * 4 + j) * 72 + r] = hh[j];
    }
    __syncthreads();
    // kv x^T tile: block (b*8+ct)*64 + nt : [ch 64][n 64] swizzled
    const size_t tbase = ((size_t)((b * 8 + ct) * 64 + nt)) * 8192;
#pragma unroll
    for (int w = 0; w < 2; w++) {
        int id = tid + w * 256;
        int ch = id >> 3, seg = id & 7;
        uint4 v = *(const uint4*)(s_hi + ch * 72 + seg * 8);
        *(uint4*)((char*)g_xT + tbase + sw128(ch * 128 + seg * 16)) = v;
    }
}

// ============================================================================
// K0b: Wqk -> GEMM-B tiled/swizzled fp16
// ============================================================================
__global__ __launch_bounds__(256) void k_convert_w(const float* __restrict__ W) {
    int idx = blockIdx.x * 256 + threadIdx.x;
    int j = idx >> 7, q4 = idx & 127;
    float4 v = *(const float4*)(W + (size_t)j * KDIM + q4 * 4);
    unsigned short hh[4] = {f2h(v.x), f2h(v.y), f2h(v.z), f2h(v.w)};
    uint2 hp;
    hp.x = (uint32_t)hh[1] << 16 | hh[0];
    hp.y = (uint32_t)hh[3] << 16 | hh[2];
    size_t base = ((size_t)(j >> 7) * 8 + (q4 >> 4)) * 16384;
    *(uint2*)((char*)g_wB + base + sw128((j & 127) * 128 + (q4 & 15) * 8)) = hp;
}

// ============================================================================
// K1: HMMA fp16 GEMM qk = x @ Wqk^T; cp.async.bulk 3-stage mbarrier pipeline.
// BK=64 (one SW128 tile per stage per operand). Fused bias/elu+1/RoPE epilogue.
// ============================================================================
#define STG_BYTES 32768          /* A 16KB + B 16KB */
#define GEMM_SMEM (3 * STG_BYTES + 1024)

__global__ __launch_bounds__(256, 2) void k_gemm_mma(const float* __restrict__ bqk) {
    extern __shared__ char dsm[];
    __shared__ long long s_mbar[3];
    const uint32_t dynb  = smem_u32(dsm);
    const uint32_t tile0 = (dynb + 1023) & ~1023u;

    const int tid = threadIdx.x;
    const int wid = tid >> 5, lid = tid & 31;
    const int jt  = blockIdx.x;            // 0..7
    const int mt  = blockIdx.y;            // 0..255
    const int j00 = jt * 128;
    const int m00 = mt * 128;
    const int warp_m = (wid >> 2) * 64;
    const int n0     = (wid & 3) * 32;

    uint32_t mb[3] = {smem_u32(&s_mbar[0]), smem_u32(&s_mbar[1]),
                      smem_u32(&s_mbar[2])};
    if (tid == 0)
#pragma unroll
        for (int s = 0; s < 3; s++) MBAR_INIT(mb[s], 1);
    __syncthreads();

    auto issue = [&](int it) {
        int s = it % 3;
        MBAR_EXPECT_TX(mb[s], STG_BYTES);
        bulk_g2s(tile0 + s * STG_BYTES,
                 (char*)g_xA + ((size_t)mt * 8 + it) * 16384, 16384, mb[s]);
        bulk_g2s(tile0 + s * STG_BYTES + 16384,
                 (char*)g_wB + ((size_t)jt * 8 + it) * 16384, 16384, mb[s]);
    };
    if (tid == 0) { issue(0); issue(1); issue(2); }

    float acc[4][4][4] = {};
    const int a_r = (lid & 15);
    const int a_c = (lid >> 4);
    const int b_r = (lid & 7) + ((lid >> 4) << 3);
    const int b_c = (lid >> 3) & 1;

    for (int it = 0; it < 8; ++it) {
        const int s = it % 3;
        MBAR_WAIT(mb[s], (it / 3) & 1);
        const uint32_t ab = tile0 + s * STG_BYTES;
        const uint32_t bb = ab + 16384;
#pragma unroll
        for (int ks = 0; ks < 4; ++ks) {
            uint32_t ah[4][4], bh[4][2];
#pragma unroll
            for (int mf = 0; mf < 4; mf++) {
                uint32_t off = (uint32_t)(warp_m + mf * 16 + a_r) * 128 +
                               ks * 32 + a_c * 16;
                ldmx4(ah[mf], ab + sw128(off));
            }
#pragma unroll
            for (int nf2 = 0; nf2 < 2; nf2++) {
                uint32_t off = (uint32_t)(n0 + nf2 * 16 + b_r) * 128 +
                               ks * 32 + b_c * 16;
                uint32_t t[4];
                ldmx4(t, bb + sw128(off));
                bh[nf2 * 2][0] = t[0]; bh[nf2 * 2][1] = t[1];
                bh[nf2 * 2 + 1][0] = t[2]; bh[nf2 * 2 + 1][1] = t[3];
            }
#pragma unroll
            for (int mf = 0; mf < 4; mf++)
#pragma unroll
                for (int nf = 0; nf < 4; nf++)
                    mma16816(acc[mf][nf], ah[mf], bh[nf]);
        }
        __syncthreads();
        if (it + 3 < 8 && tid == 0) { FENCE_ASYNC(); issue(it + 3); }
    }

    // ---------------- epilogue ----------------
    unsigned short* s_p0 = (unsigned short*)dsm;               // 128x136
    unsigned short* s_p1 = s_p0 + 128 * 136;
    float*          s_red = (float*)(s_p1 + 128 * 136);        // 2x128

    const bool is_k = (j00 >= CC);
    const int  jbase = (is_k ? j00 - CC : j00) + n0 + 2 * (lid & 3);
    float th[4], bx[4], by[4];
    bool  uhc[4];
#pragma unroll
    for (int nf = 0; nf < 4; nf++) {
        int jch = jbase + nf * 8;
        int j2  = jch >> 1;
        int jm  = j2 & 127;
        th[nf]  = exp2f(-(float)jm * (13.287712379549449f / 128.0f));
        uhc[nf] = (j2 < 128);
        float2 bv = *(const float2*)(bqk + j00 + n0 + nf * 8 + 2 * (lid & 3));
        bx[nf] = bv.x;
        by[nf] = bv.y;
    }

    float fsum[4][2] = {};
#pragma unroll
    for (int mf = 0; mf < 4; mf++)
#pragma unroll
        for (int ri = 0; ri < 2; ri++) {
            int   r_loc = warp_m + mf * 16 + (lid >> 2) + ri * 8;
            int   n  = (m00 + r_loc) & (NPOS - 1);
            float hf = (float)(n >> 6);
            float wf = (float)(n & 63);
#pragma unroll
            for (int nf = 0; nf < 4; nf++) {
                float v0 = acc[mf][nf][ri * 2 + 0] + bx[nf];
                float v1 = acc[mf][nf][ri * 2 + 1] + by[nf];
                float f0 = (v0 > 0.f) ? (v0 + 1.f) : __expf(v0);
                float f1 = (v1 > 0.f) ? (v1 + 1.f) : __expf(v1);
                float s, c;
                __sincosf((uhc[nf] ? hf : wf) * th[nf], &s, &c);
                float ro0 = c * f0 - s * f1;
                float ro1 = c * f1 + s * f0;
                int c_loc = n0 + nf * 8 + 2 * (lid & 3);
                if (!is_k) {
                    s_p0[r_loc * 136 + c_loc]     = f2h(ro0);
                    s_p0[r_loc * 136 + c_loc + 1] = f2h(ro1);
                    s_p1[r_loc * 136 + c_loc]     = f2h(f0);
                    s_p1[r_loc * 136 + c_loc + 1] = f2h(f1);
                } else {
                    s_p0[c_loc * 136 + r_loc]       = f2h(ro0);
                    s_p0[(c_loc + 1) * 136 + r_loc] = f2h(ro1);
                    fsum[nf][0] += f0;
                    fsum[nf][1] += f1;
                }
            }
        }

    if (is_k) {
#pragma unroll
        for (int off = 4; off < 32; off <<= 1)
#pragma unroll
            for (int nf = 0; nf < 4; nf++) {
                fsum[nf][0] += __shfl_xor_sync(0xffffffffu, fsum[nf][0], off);
                fsum[nf][1] += __shfl_xor_sync(0xffffffffu, fsum[nf][1], off);
            }
        if (lid < 4) {
#pragma unroll
            for (int nf = 0; nf < 4; nf++) {
                s_red[(wid >> 2) * 128 + n0 + nf * 8 + 2 * lid]     = fsum[nf][0];
                s_red[(wid >> 2) * 128 + n0 + nf * 8 + 2 * lid + 1] = fsum[nf][1];
            }
        }
    }
    __syncthreads();

    if (!is_k) {
        const int r    = tid >> 1;
        const int half = tid & 1;
        size_t drow = (size_t)(m00 + r) * CC + j00 + half * 64;
        const uint4* sp0 = (const uint4*)(s_p0 + r * 136 + half * 64);
        const uint4* sp1 = (const uint4*)(s_p1 + r * 136 + half * 64);
        uint4* d0 = (uint4*)(g_qr + drow);
        uint4* d1 = (uint4*)(g_qf + drow);
#pragma unroll
        for (int i = 0; i < 8; i++) { d0[i] = sp0[i]; d1[i] = sp1[i]; }
    } else {
        // write k_rope^T into kv-tiled swizzled layout (4 blocks of 64x64)
        const int b      = m00 >> 12;
        const int n0g    = m00 & (NPOS - 1);
        const int cblk0  = (jt - 4) * 2;
#pragma unroll
        for (int w = 0; w < 8; w++) {
            int id  = tid + w * 256;
            int blk = id >> 9;          // 0..3
            int cb  = blk >> 1, nb = blk & 1;
            int within = id & 511;
            int ch = within >> 3, seg = within & 7;
            size_t base = ((size_t)((b * 8 + cblk0 + cb) * 64) +
                           (n0g >> 6) + nb) * 8192;
            uint4 v = *(const uint4*)(s_p0 + (cb * 64 + ch) * 136 + nb * 64 + seg * 8);
            *(uint4*)((char*)g_krT + base + sw128(ch * 128 + seg * 16)) = v;
        }
        if (tid < 128)
            g_kspart[(size_t)mt * CC + (jt - 4) * 128 + tid] =
                s_red[tid] + s_red[128 + tid];
    }
}

// ============================================================================
// K1c: ksum final — sum 32 mtile partials per batch
// ============================================================================
__global__ void k_ksum_final() {
    int idx = blockIdx.x * 256 + threadIdx.x;  // 0..4095
    if (idx < BB * CC) {
        int b = idx >> 9, ch = idx & 511;
        float s = 0.f;
        for (int mt = b * 32; mt < b * 32 + 32; mt++)
            s += g_kspart[(size_t)mt * CC + ch];
        g_ksum[idx] = s;
    }
}

// ============================================================================
// K2: kv partials via HMMA + bulk-copy pipeline over pre-swizzled 8KB tiles
// ============================================================================
#define KV_STG 16384
#define KV_SMEM (3 * KV_STG + 1024)

__global__ __launch_bounds__(128) void k_kv_mma() {
    extern __shared__ char ksm[];
    __shared__ long long s_mbar[3];
    const uint32_t dynb  = smem_u32(ksm);
    const uint32_t tile0 = (dynb + 1023) & ~1023u;
    const int tid = threadIdx.x;
    const int wid = tid >> 5, lid = tid & 31;
    const int chunk = blockIdx.x;          // 0..7
    const int bh    = blockIdx.y;          // 0..63
    const int b = bh >> 3, h = bh & 7;
    const size_t blk0 = (size_t)(b * 8 + h) * 64 + chunk * 8;

    uint32_t mb[3] = {smem_u32(&s_mbar[0]), smem_u32(&s_mbar[1]),
                      smem_u32(&s_mbar[2])};
    if (tid == 0)
#pragma unroll
        for (int s = 0; s < 3; s++) MBAR_INIT(mb[s], 1);
    __syncthreads();

    auto issue = [&](int it) {
        int s = it % 3;
        MBAR_EXPECT_TX(mb[s], KV_STG);
        bulk_g2s(tile0 + s * KV_STG, (char*)g_krT + (blk0 + it) * 8192, 8192, mb[s]);
        bulk_g2s(tile0 + s * KV_STG + 8192, (char*)g_xT + (blk0 + it) * 8192, 8192,
                 mb[s]);
    };
    if (tid == 0) { issue(0); issue(1); issue(2); }

    float acc[8][4] = {};
    const int a_r = (lid & 15);
    const int a_c = (lid >> 4);
    const int b_r = (lid & 7) + ((lid >> 4) << 3);
    const int b_c = (lid >> 3) & 1;

    for (int it = 0; it < 8; ++it) {
        const int s = it % 3;
        MBAR_WAIT(mb[s], (it / 3) & 1);
        const uint32_t ab = tile0 + s * KV_STG;
        const uint32_t bb = ab + 8192;
#pragma unroll
        for (int ks = 0; ks < 4; ++ks) {
            uint32_t ah[4];
            ldmx4(ah, ab + sw128((uint32_t)(wid * 16 + a_r) * 128 + ks * 32 + a_c * 16));
            uint32_t bhf[8][2];
#pragma unroll
            for (int e2 = 0; e2 < 4; e2++) {
                uint32_t t[4];
                ldmx4(t, bb + sw128((uint32_t)(e2 * 16 + b_r) * 128 + ks * 32 + b_c * 16));
                bhf[e2 * 2][0] = t[0]; bhf[e2 * 2][1] = t[1];
                bhf[e2 * 2 + 1][0] = t[2]; bhf[e2 * 2 + 1][1] = t[3];
            }
#pragma unroll
            for (int ef = 0; ef < 8; ef++) mma16816(acc[ef], ah, bhf[ef]);
        }
        __syncthreads();
        if (it + 3 < 8 && tid == 0) { FENCE_ASYNC(); issue(it + 3); }
    }

    float* dst = g_kv_part + (size_t)(chunk * 64 + bh) * (DH * DH);
    const int r0 = wid * 16 + (lid >> 2);
    const int c0 = 2 * (lid & 3);
#pragma unroll
    for (int ef = 0; ef < 8; ef++) {
        *(float2*)&dst[r0 * DH + ef * 8 + c0] = make_float2(acc[ef][0], acc[ef][1]);
        *(float2*)&dst[(r0 + 8) * DH + ef * 8 + c0] = make_float2(acc[ef][2], acc[ef][3]);
    }
}

__global__ void k_kv_final() {
    int idx = blockIdx.x * 256 + threadIdx.x;
    float s = 0.f;
    for (int c2 = 0; c2 < 8; c2++) s += g_kv_part[(size_t)c2 * 64 * DH * DH + idx];
    g_kv[idx] = s * (1.0f / (float)NPOS);
}

// ============================================================================
// K3: out = (q_rope @ kv) * z + LePE(x)   (q_rope/q_feat fp16)
// ============================================================================
__global__ __launch_bounds__(256) void k_out(const float* __restrict__ x,
                                             const float* __restrict__ lepe_w,
                                             const float* __restrict__ lepe_b,
                                             float* __restrict__ out) {
    __shared__ float s_kv[64 * 68];
    __shared__ float s_qrT[64 * 68];
    __shared__ float s_z[64];
    __shared__ float s_km[64];

    int ntile = blockIdx.x;
    int hh    = blockIdx.y;
    int b     = blockIdx.z;
    int tid   = threadIdx.x;
    int n0    = ntile * 64;

#pragma unroll
    for (int i = 0; i < 4; i++) {
        int f = tid + i * 256;
        int r = f >> 4, cu = f & 15;
        uint2 v = *(const uint2*)(g_qf + (size_t)(b * NPOS + n0 + r) * CC +
                                  hh * DH + cu * 4);
        s_kv[r * 68 + cu * 4 + 0] = h2f((unsigned short)(v.x & 0xffff));
        s_kv[r * 68 + cu * 4 + 1] = h2f((unsigned short)(v.x >> 16));
        s_kv[r * 68 + cu * 4 + 2] = h2f((unsigned short)(v.y & 0xffff));
        s_kv[r * 68 + cu * 4 + 3] = h2f((unsigned short)(v.y >> 16));
    }
    if (tid < 64) s_km[tid] = g_ksum[b * CC + hh * DH + tid] * (1.0f / (float)NPOS);
    __syncthreads();

    if (tid < 64) {
        float dot = 0.f;
#pragma unroll
        for (int dd = 0; dd < 64; dd++) dot += s_kv[tid * 68 + dd] * s_km[dd];
        s_z[tid] = 1.0f / (dot + 1e-6f);
    }
    __syncthreads();

#pragma unroll
    for (int i = 0; i < 4; i++) {
        int f = tid + i * 256;
        int r = f >> 4, cu = f & 15;
        *(float4*)&s_kv[r * 68 + cu * 4] =
            *(const float4*)(g_kv + (size_t)(b * NH + hh) * DH * DH + r * DH + cu * 4);
        uint2 v = *(const uint2*)(g_qr + (size_t)(b * NPOS + n0 + r) * CC +
                                  hh * DH + cu * 4);
        s_qrT[(cu * 4 + 0) * 68 + r] = h2f((unsigned short)(v.x & 0xffff));
        s_qrT[(cu * 4 + 1) * 68 + r] = h2f((unsigned short)(v.x >> 16));
        s_qrT[(cu * 4 + 2) * 68 + r] = h2f((unsigned short)(v.y & 0xffff));
        s_qrT[(cu * 4 + 3) * 68 + r] = h2f((unsigned short)(v.y >> 16));
    }
    __syncthreads();

    int ty = tid >> 4, tx = tid & 15;
    int r0 = ty * 4, e0 = tx * 4;
    float acc[4][4] = {};
#pragma unroll
    for (int dd = 0; dd < 64; dd++) {
        float4 a  = *(const float4*)&s_qrT[dd * 68 + r0];
        float4 bv = *(const float4*)&s_kv[dd * 68 + e0];
        float av[4]  = {a.x, a.y, a.z, a.w};
        float bb2[4] = {bv.x, bv.y, bv.z, bv.w};
#pragma unroll
        for (int i = 0; i < 4; i++)
#pragma unroll
            for (int j = 0; j < 4; j++) acc[i][j] += av[i] * bb2[j];
    }

    const int hi = ntile;
    float wloc[4][9], bloc[4];
#pragma unroll
    for (int j = 0; j < 4; j++) {
        int ch = hh * DH + e0 + j;
        bloc[j] = lepe_b[ch];
#pragma unroll
        for (int q = 0; q < 9; q++) wloc[j][q] = lepe_w[ch * 9 + q];
    }
#pragma unroll
    for (int ri = 0; ri < 4; ri++) {
        int r  = r0 + ri;
        int wi = r;
        int nn = n0 + r;
        float z = s_z[r];
#pragma unroll
        for (int j = 0; j < 4; j++) {
            int ch = hh * DH + e0 + j;
            float pe = bloc[j];
#pragma unroll
            for (int dy = -1; dy <= 1; dy++) {
                int y = hi + dy;
                if ((unsigned)y < 64u) {
#pragma unroll
                    for (int dx = -1; dx <= 1; dx++) {
                        int xw = wi + dx;
                        if ((unsigned)xw < 64u)
                            pe += wloc[j][(dy + 1) * 3 + dx + 1] *
                                  x[((size_t)b * NPOS + y * 64 + xw) * CC + ch];
                    }
                }
            }
            out[((size_t)b * NPOS + nn) * CC + ch] = acc[ri][j] * z + pe;
        }
    }
}

// ============================================================================
extern "C" void kernel_launch(void* const* d_in, const int* in_sizes, int n_in,
                              void* d_out, int out_size) {
    const float *x = nullptr, *Wqk = nullptr, *bqk = nullptr;
    const float *lw = nullptr, *lb = nullptr;
    for (int i = 0; i < n_in; i++) {
        switch (in_sizes[i]) {
            case BB * NPOS * CC: x   = (const float*)d_in[i]; break;
            case 2 * CC * CC:    Wqk = (const float*)d_in[i]; break;
            case 2 * CC:         bqk = (const float*)d_in[i]; break;
            case CC * 9:         lw  = (const float*)d_in[i]; break;
            case CC:             lb  = (const float*)d_in[i]; break;
            default: break;  // h, w scalars
        }
    }
    float* out = (float*)d_out;

    cudaFuncSetAttribute(k_gemm_mma, cudaFuncAttributeMaxDynamicSharedMemorySize,
                         GEMM_SMEM);
    cudaFuncSetAttribute(k_kv_mma, cudaFuncAttributeMaxDynamicSharedMemorySize,
                         KV_SMEM);

    // 4 prep launches + convert_w => k_gemm_mma is launch index 5 (ncu -s 5 -c 1)
    k_prep_x<<<dim3(8, 64, 2), 256>>>(x, 0);
    k_prep_x<<<dim3(8, 64, 2), 256>>>(x, 2);
    k_prep_x<<<dim3(8, 64, 2), 256>>>(x, 4);
    k_prep_x<<<dim3(8, 64, 2), 256>>>(x, 6);
    k_convert_w<<<512, 256>>>(Wqk);
    k_gemm_mma<<<dim3(8, 256), 256, GEMM_SMEM>>>(bqk);
    k_ksum_final<<<16, 256>>>();
    k_kv_mma<<<dim3(8, 64), 128, KV_SMEM>>>();
    k_kv_final<<<1024, 256>>>();
    k_out<<<dim3(64, 8, 8), 256>>>(x, lw, lb, out);
}